// round 6
// baseline (speedup 1.0000x reference)
#include <cuda_runtime.h>
#include <math.h>

// Problem dims
#define BB   32
#define LL   512
#define EE   768
#define HH   1024
#define OO   128
#define BL   (BB * LL)          // 16384

// ---------------------------------------------------------------------------
// Static scratch (allocation-free)
// ---------------------------------------------------------------------------
__device__ float g_xp[(size_t)BL * HH];
__device__ float g_r1[(size_t)BL * HH];
__device__ float g_r2[(size_t)BL * HH];

// per-batch-group barrier state, each on its own 128B line
__device__ unsigned g_cnt4[4 * 32];
__device__ unsigned g_flag4[4 * 32];

#define SEL_EXT 0
#define SEL_R1  1
#define SEL_R2  2
#define SEL_XP  3

__device__ __forceinline__ const float* pick_src(int sel, const float* ext) {
    if (sel == SEL_R1) return g_r1;
    if (sel == SEL_R2) return g_r2;
    if (sel == SEL_XP) return g_xp;
    return ext;
}
__device__ __forceinline__ float* pick_dst(int sel, float* ext) {
    if (sel == SEL_XP) return g_xp;
    if (sel == SEL_R1) return g_r1;
    if (sel == SEL_R2) return g_r2;
    return ext;
}

// packed f32x2 fma: acc = a*b + acc (two fp32 MACs per instruction)
__device__ __forceinline__ void fma2(unsigned long long& acc,
                                     unsigned long long a,
                                     unsigned long long b) {
    asm("fma.rn.f32x2 %0, %1, %2, %0;" : "+l"(acc) : "l"(a), "l"(b));
}
__device__ __forceinline__ float lo32(unsigned long long v) {
    return __uint_as_float((unsigned)v);
}
__device__ __forceinline__ float hi32(unsigned long long v) {
    return __uint_as_float((unsigned)(v >> 32));
}

// fast tanh via MUFU: tanh(x) = 1 - 2/(e^{2x}+1)
__device__ __forceinline__ float fast_tanh(float x) {
    float xc = fminf(fmaxf(x, -15.0f), 15.0f);
    float e  = __expf(2.0f * xc);
    return 1.0f - __fdividef(2.0f, e + 1.0f);
}

// release/acquire primitives for the inter-block publish chain
__device__ __forceinline__ unsigned atom_add_acq_rel(unsigned* p, unsigned v) {
    unsigned old;
    asm volatile("atom.global.acq_rel.gpu.add.u32 %0, [%1], %2;"
                 : "=r"(old) : "l"(p), "r"(v) : "memory");
    return old;
}
__device__ __forceinline__ void st_release(unsigned* p, unsigned v) {
    asm volatile("st.global.release.gpu.u32 [%0], %1;"
                 :: "l"(p), "r"(v) : "memory");
}
__device__ __forceinline__ unsigned ld_acquire(const unsigned* p) {
    unsigned v;
    asm volatile("ld.global.acquire.gpu.u32 %0, [%1];"
                 : "=r"(v) : "l"(p) : "memory");
    return v;
}

// ---------------------------------------------------------------------------
// SGEMM: C[M,N] = A[M,K] * W[N,K]^T + bias1[n] (+ bias2[n])
// 128x128 tile, BK=8, 256 threads, 8x8/thread, f32x2 FMA, double-buffered.
// ---------------------------------------------------------------------------
#define BM 128
#define BN 128
#define BK 8

__global__ __launch_bounds__(256) void sgemm_bias(
    const float* __restrict__ Aext, int Asel,
    const float* __restrict__ W,
    float* __restrict__ Cext, int Csel,
    const float* __restrict__ bias1, const float* __restrict__ bias2,
    int M, int N, int K)
{
    const float* A = pick_src(Asel, Aext);
    float* C = pick_dst(Csel, Cext);

    __shared__ float As[2][BK][BM];
    __shared__ float Bs[2][BK][BN];

    const int tid = threadIdx.x;
    const int tx = tid & 15;
    const int ty = tid >> 4;
    const int m0 = blockIdx.y * BM;
    const int n0 = blockIdx.x * BN;

    const int la_r = tid >> 1;
    const int la_k = (tid & 1) * 4;

    unsigned long long acc[8][4];
    #pragma unroll
    for (int i = 0; i < 8; i++)
        #pragma unroll
        for (int j = 0; j < 4; j++) acc[i][j] = 0ull;

    float4 av = *(const float4*)(A + (size_t)(m0 + la_r) * K + la_k);
    float4 bv = *(const float4*)(W + (size_t)(n0 + la_r) * K + la_k);

    int buf = 0;
    for (int k0 = 0; k0 < K; k0 += BK) {
        As[buf][la_k + 0][la_r] = av.x; As[buf][la_k + 1][la_r] = av.y;
        As[buf][la_k + 2][la_r] = av.z; As[buf][la_k + 3][la_r] = av.w;
        Bs[buf][la_k + 0][la_r] = bv.x; Bs[buf][la_k + 1][la_r] = bv.y;
        Bs[buf][la_k + 2][la_r] = bv.z; Bs[buf][la_k + 3][la_r] = bv.w;
        __syncthreads();

        if (k0 + BK < K) {
            av = *(const float4*)(A + (size_t)(m0 + la_r) * K + k0 + BK + la_k);
            bv = *(const float4*)(W + (size_t)(n0 + la_r) * K + k0 + BK + la_k);
        }

        #pragma unroll
        for (int kk = 0; kk < BK; kk++) {
            float a[8];
            *(float4*)(a)     = *(const float4*)&As[buf][kk][ty * 4];
            *(float4*)(a + 4) = *(const float4*)&As[buf][kk][ty * 4 + 64];
            ulonglong2 bv0 = *(const ulonglong2*)&Bs[buf][kk][tx * 4];
            ulonglong2 bv1 = *(const ulonglong2*)&Bs[buf][kk][tx * 4 + 64];
            unsigned long long bp[4] = {bv0.x, bv0.y, bv1.x, bv1.y};
            #pragma unroll
            for (int i = 0; i < 8; i++) {
                unsigned long long ap;
                unsigned ai = __float_as_uint(a[i]);
                asm("mov.b64 %0, {%1, %1};" : "=l"(ap) : "r"(ai));
                #pragma unroll
                for (int jp = 0; jp < 4; jp++)
                    fma2(acc[i][jp], ap, bp[jp]);
            }
        }
        buf ^= 1;
    }

    #pragma unroll
    for (int jg = 0; jg < 2; jg++) {
        const int n = n0 + tx * 4 + jg * 64;
        float4 bb = make_float4(0.f, 0.f, 0.f, 0.f);
        if (bias1) {
            float4 t = *(const float4*)(bias1 + n);
            bb.x += t.x; bb.y += t.y; bb.z += t.z; bb.w += t.w;
        }
        if (bias2) {
            float4 t = *(const float4*)(bias2 + n);
            bb.x += t.x; bb.y += t.y; bb.z += t.z; bb.w += t.w;
        }
        #pragma unroll
        for (int i = 0; i < 8; i++) {
            const int ml = (i < 4) ? (ty * 4 + i) : (64 + ty * 4 + i - 4);
            const int m  = m0 + ml;
            unsigned long long p0 = acc[i][jg * 2 + 0];
            unsigned long long p1 = acc[i][jg * 2 + 1];
            float4 v;
            v.x = lo32(p0) + bb.x;
            v.y = hi32(p0) + bb.y;
            v.z = lo32(p1) + bb.z;
            v.w = hi32(p1) + bb.w;
            *(float4*)(C + (size_t)m * N + n) = v;
        }
    }
}

// ---------------------------------------------------------------------------
// Persistent RNN layer: r[:,t,:] = tanh(xp[:,t,:] + r[:,t-1,:] @ W_hh^T)
//
// Grid: 128 blocks = 4 batch-groups (8 batches) x 32 col-groups (32 cols).
// Block: 512 threads = 16 warps; warp <-> k-chunk (64 k), lane <-> col.
//
// Inter-block step barrier (per group of 32 blocks):
//   producers (warps 0-7) store h_t -> bar.sync 1,256 -> tid0
//   atom.add.acq_rel on the group counter; LAST arriver st.release's
//   the group flag = t+1. ALL warps of all blocks poll the flag with
//   ld.acquire (one broadcast L2 word) and immediately stage warp-locally.
//   No threadfence, no tid0-spin-then-syncthreads wake chain.
// ---------------------------------------------------------------------------
#define WPAD 1028                      // 1028 % 32 == 4 -> conflict-free LDS.128
#define RNN_BLOCKS 128
#define RNN_SMEM_FLOATS (32 * WPAD + 16 * 512 + 16 * 256)

__global__ __launch_bounds__(512) void rnn_layer_kernel(
    int rsel, const float* __restrict__ W)
{
    float* r = (rsel == SEL_R1) ? g_r1 : g_r2;

    extern __shared__ float sm[];
    float* Wsm = sm;                        // 32 x WPAD
    float* hsm = sm + 32 * WPAD;            // 16 warps x (8 x 64)
    float* psm = sm + 32 * WPAD + 16 * 512; // 16 x 8 x 32 partials

    const int tid  = threadIdx.x;
    const int warp = tid >> 5;              // k-chunk 0..15
    const int lane = tid & 31;              // col within group
    const int bg = blockIdx.x >> 5;         // 0..3
    const int cg = blockIdx.x & 31;         // 0..31
    const int b0 = bg * 8;
    const int c0 = cg * 32;
    const int kbase = warp * 64;

    unsigned* cnt  = &g_cnt4[bg * 32];
    unsigned* flag = &g_flag4[bg * 32];

    // stage W rows c0..c0+31 (full K) once
    #pragma unroll
    for (int i = tid; i < 8192; i += 512) {
        const int rr = i >> 8;
        const int q  = (i & 255) << 2;
        *(float4*)&Wsm[rr * WPAD + q] =
            *(const float4*)(W + (size_t)(c0 + rr) * HH + q);
    }
    __syncthreads();

    const ulonglong2* wp = (const ulonglong2*)&Wsm[lane * WPAD + kbase];
    float* hw = &hsm[warp * 512];

    const float* xp_ptr = g_xp + ((size_t)(b0 + warp) * LL) * HH + (c0 + lane);
    float*       r_ptr  = r    + ((size_t)(b0 + warp) * LL) * HH + (c0 + lane);

    for (int t = 0; t < LL; t++) {
        float xq = 0.0f;
        if (t > 0) {
            // wait for h_{t-1} publication (acquire; all lanes, broadcast read)
            while (ld_acquire(flag) < (unsigned)t) { }

            // warp-local h staging: 4 float4 per thread (own k-chunk, 8 rows)
            const float* hsrc = r + (size_t)(t - 1) * HH + kbase;
            #pragma unroll
            for (int j = 0; j < 4; j++) {
                const int i  = j * 32 + lane;
                const int rr = i >> 4;            // 0..7
                const int qq = (i & 15) << 2;     // 0..60
                *(float4*)&hw[rr * 64 + qq] =
                    *(const float4*)(hsrc + (size_t)(b0 + rr) * LL * HH + qq);
            }
            __syncwarp();

            if (warp < 8) xq = __ldg(xp_ptr + (size_t)t * HH);

            unsigned long long acc[8];
            #pragma unroll
            for (int b = 0; b < 8; b++) acc[b] = 0ull;

            #pragma unroll 4
            for (int q = 0; q < 16; q++) {
                const ulonglong2 wv = wp[q];
                #pragma unroll
                for (int b = 0; b < 8; b++) {
                    const ulonglong2 hv = *(const ulonglong2*)&hw[b * 64 + q * 4];
                    fma2(acc[b], wv.x, hv.x);
                    fma2(acc[b], wv.y, hv.y);
                }
            }

            #pragma unroll
            for (int b = 0; b < 8; b++)
                psm[warp * 256 + b * 32 + lane] = lo32(acc[b]) + hi32(acc[b]);
            __syncthreads();
        } else {
            if (warp < 8) xq = __ldg(xp_ptr);
        }

        // producers: reduce + activation + store + publish
        if (warp < 8) {
            float dot = 0.0f;
            if (t > 0) {
                #pragma unroll
                for (int w = 0; w < 16; w++)
                    dot += psm[w * 256 + warp * 32 + lane];
            }
            r_ptr[(size_t)t * HH] = fast_tanh(xq + dot);

            if (t < LL - 1) {
                asm volatile("bar.sync 1, 256;" ::: "memory");  // warps 0-7
                if (tid == 0) {
                    unsigned old = atom_add_acq_rel(cnt, 1u);
                    if (old == 32u * (unsigned)(t + 1) - 1u)
                        st_release(flag, (unsigned)(t + 1));
                }
            }
        }
        // warps 8-15 fall through to the next iteration's flag poll
    }
}

// reset barrier state (before each rnn layer -> deterministic replays)
__global__ void rnn_init_kernel()
{
    if (threadIdx.x < 4) {
        g_cnt4[threadIdx.x * 32]  = 0u;
        g_flag4[threadIdx.x * 32] = 0u;
    }
}

// ---------------------------------------------------------------------------
// Launch: 8 graph nodes
// ---------------------------------------------------------------------------
extern "C" void kernel_launch(void* const* d_in, const int* in_sizes, int n_in,
                              void* d_out, int out_size)
{
    const float* x     = (const float*)d_in[0];
    const float* W_ih1 = (const float*)d_in[1];
    const float* W_hh1 = (const float*)d_in[2];
    const float* b_ih1 = (const float*)d_in[3];
    const float* b_hh1 = (const float*)d_in[4];
    const float* W_ih2 = (const float*)d_in[5];
    const float* W_hh2 = (const float*)d_in[6];
    const float* b_ih2 = (const float*)d_in[7];
    const float* b_hh2 = (const float*)d_in[8];
    const float* W1    = (const float*)d_in[9];
    const float* b1    = (const float*)d_in[10];
    const float* W2    = (const float*)d_in[11];
    const float* b2    = (const float*)d_in[12];
    float* out = (float*)d_out;

    static int smem_set = 0;
    if (!smem_set) {
        cudaFuncSetAttribute(rnn_layer_kernel,
                             cudaFuncAttributeMaxDynamicSharedMemorySize,
                             RNN_SMEM_FLOATS * sizeof(float));
        smem_set = 1;
    }
    const size_t rnn_smem = RNN_SMEM_FLOATS * sizeof(float);

    const dim3 gBig(HH / BN, BL / BM);   // (8, 128)
    const dim3 gOut(OO / BN, BL / BM);   // (1, 128)

    sgemm_bias<<<gBig, 256>>>(x, SEL_EXT, W_ih1, nullptr, SEL_XP,
                              b_ih1, b_hh1, BL, HH, EE);
    rnn_init_kernel<<<1, 32>>>();
    rnn_layer_kernel<<<RNN_BLOCKS, 512, rnn_smem>>>(SEL_R1, W_hh1);

    sgemm_bias<<<gBig, 256>>>(nullptr, SEL_R1, W_ih2, nullptr, SEL_XP,
                              b_ih2, b_hh2, BL, HH, HH);
    rnn_init_kernel<<<1, 32>>>();
    rnn_layer_kernel<<<RNN_BLOCKS, 512, rnn_smem>>>(SEL_R2, W_hh2);

    sgemm_bias<<<gOut, 256>>>(nullptr, SEL_R1, W1, out, SEL_EXT,
                              b1, nullptr, BL, OO, HH);
    sgemm_bias<<<gOut, 256>>>(nullptr, SEL_R2, W2, out + (size_t)BL * OO, SEL_EXT,
                              b2, nullptr, BL, OO, HH);
}

// round 7
// speedup vs baseline: 1.1155x; 1.1155x over previous
#include <cuda_runtime.h>
#include <math.h>

// Problem dims
#define BB   32
#define LL   512
#define EE   768
#define HH   1024
#define OO   128
#define BL   (BB * LL)          // 16384

// ---------------------------------------------------------------------------
// Static scratch (allocation-free)
// ---------------------------------------------------------------------------
__device__ float g_xp[(size_t)BL * HH];
__device__ float g_r1[(size_t)BL * HH];
__device__ float g_r2[(size_t)BL * HH];

// per-batch-group barrier state, each on its own 128B line
__device__ unsigned g_cnt4[4 * 32];
__device__ unsigned g_flag4[4 * 32];

#define SEL_EXT 0
#define SEL_R1  1
#define SEL_R2  2
#define SEL_XP  3

__device__ __forceinline__ const float* pick_src(int sel, const float* ext) {
    if (sel == SEL_R1) return g_r1;
    if (sel == SEL_R2) return g_r2;
    if (sel == SEL_XP) return g_xp;
    return ext;
}
__device__ __forceinline__ float* pick_dst(int sel, float* ext) {
    if (sel == SEL_XP) return g_xp;
    if (sel == SEL_R1) return g_r1;
    if (sel == SEL_R2) return g_r2;
    return ext;
}

// packed f32x2 fma: acc = a*b + acc
__device__ __forceinline__ void fma2(unsigned long long& acc,
                                     unsigned long long a,
                                     unsigned long long b) {
    asm("fma.rn.f32x2 %0, %1, %2, %0;" : "+l"(acc) : "l"(a), "l"(b));
}
__device__ __forceinline__ float lo32(unsigned long long v) {
    return __uint_as_float((unsigned)v);
}
__device__ __forceinline__ float hi32(unsigned long long v) {
    return __uint_as_float((unsigned)(v >> 32));
}

// fast tanh via MUFU: tanh(x) = 1 - 2/(e^{2x}+1)
__device__ __forceinline__ float fast_tanh(float x) {
    float xc = fminf(fmaxf(x, -15.0f), 15.0f);
    float e  = __expf(2.0f * xc);
    return 1.0f - __fdividef(2.0f, e + 1.0f);
}

// release/acquire primitives
__device__ __forceinline__ unsigned atom_add_acq_rel(unsigned* p, unsigned v) {
    unsigned old;
    asm volatile("atom.global.acq_rel.gpu.add.u32 %0, [%1], %2;"
                 : "=r"(old) : "l"(p), "r"(v) : "memory");
    return old;
}
__device__ __forceinline__ void st_release(unsigned* p, unsigned v) {
    asm volatile("st.global.release.gpu.u32 [%0], %1;"
                 :: "l"(p), "r"(v) : "memory");
}
__device__ __forceinline__ unsigned ld_acquire(const unsigned* p) {
    unsigned v;
    asm volatile("ld.global.acquire.gpu.u32 %0, [%1];"
                 : "=r"(v) : "l"(p) : "memory");
    return v;
}

// ---------------------------------------------------------------------------
// SGEMM: C[M,N] = A[M,K] * W[N,K]^T + bias1[n] (+ bias2[n])
// 128x128 tile, BK=8, 256 threads, 8x8/thread, f32x2 FMA, double-buffered.
// ---------------------------------------------------------------------------
#define BM 128
#define BN 128
#define BK 8

__global__ __launch_bounds__(256) void sgemm_bias(
    const float* __restrict__ Aext, int Asel,
    const float* __restrict__ W,
    float* __restrict__ Cext, int Csel,
    const float* __restrict__ bias1, const float* __restrict__ bias2,
    int M, int N, int K)
{
    const float* A = pick_src(Asel, Aext);
    float* C = pick_dst(Csel, Cext);

    __shared__ float As[2][BK][BM];
    __shared__ float Bs[2][BK][BN];

    const int tid = threadIdx.x;
    const int tx = tid & 15;
    const int ty = tid >> 4;
    const int m0 = blockIdx.y * BM;
    const int n0 = blockIdx.x * BN;

    const int la_r = tid >> 1;
    const int la_k = (tid & 1) * 4;

    unsigned long long acc[8][4];
    #pragma unroll
    for (int i = 0; i < 8; i++)
        #pragma unroll
        for (int j = 0; j < 4; j++) acc[i][j] = 0ull;

    float4 av = *(const float4*)(A + (size_t)(m0 + la_r) * K + la_k);
    float4 bv = *(const float4*)(W + (size_t)(n0 + la_r) * K + la_k);

    int buf = 0;
    for (int k0 = 0; k0 < K; k0 += BK) {
        As[buf][la_k + 0][la_r] = av.x; As[buf][la_k + 1][la_r] = av.y;
        As[buf][la_k + 2][la_r] = av.z; As[buf][la_k + 3][la_r] = av.w;
        Bs[buf][la_k + 0][la_r] = bv.x; Bs[buf][la_k + 1][la_r] = bv.y;
        Bs[buf][la_k + 2][la_r] = bv.z; Bs[buf][la_k + 3][la_r] = bv.w;
        __syncthreads();

        if (k0 + BK < K) {
            av = *(const float4*)(A + (size_t)(m0 + la_r) * K + k0 + BK + la_k);
            bv = *(const float4*)(W + (size_t)(n0 + la_r) * K + k0 + BK + la_k);
        }

        #pragma unroll
        for (int kk = 0; kk < BK; kk++) {
            float a[8];
            *(float4*)(a)     = *(const float4*)&As[buf][kk][ty * 4];
            *(float4*)(a + 4) = *(const float4*)&As[buf][kk][ty * 4 + 64];
            ulonglong2 bv0 = *(const ulonglong2*)&Bs[buf][kk][tx * 4];
            ulonglong2 bv1 = *(const ulonglong2*)&Bs[buf][kk][tx * 4 + 64];
            unsigned long long bp[4] = {bv0.x, bv0.y, bv1.x, bv1.y};
            #pragma unroll
            for (int i = 0; i < 8; i++) {
                unsigned long long ap;
                unsigned ai = __float_as_uint(a[i]);
                asm("mov.b64 %0, {%1, %1};" : "=l"(ap) : "r"(ai));
                #pragma unroll
                for (int jp = 0; jp < 4; jp++)
                    fma2(acc[i][jp], ap, bp[jp]);
            }
        }
        buf ^= 1;
    }

    #pragma unroll
    for (int jg = 0; jg < 2; jg++) {
        const int n = n0 + tx * 4 + jg * 64;
        float4 bb = make_float4(0.f, 0.f, 0.f, 0.f);
        if (bias1) {
            float4 t = *(const float4*)(bias1 + n);
            bb.x += t.x; bb.y += t.y; bb.z += t.z; bb.w += t.w;
        }
        if (bias2) {
            float4 t = *(const float4*)(bias2 + n);
            bb.x += t.x; bb.y += t.y; bb.z += t.z; bb.w += t.w;
        }
        #pragma unroll
        for (int i = 0; i < 8; i++) {
            const int ml = (i < 4) ? (ty * 4 + i) : (64 + ty * 4 + i - 4);
            const int m  = m0 + ml;
            unsigned long long p0 = acc[i][jg * 2 + 0];
            unsigned long long p1 = acc[i][jg * 2 + 1];
            float4 v;
            v.x = lo32(p0) + bb.x;
            v.y = hi32(p0) + bb.y;
            v.z = lo32(p1) + bb.z;
            v.w = hi32(p1) + bb.w;
            *(float4*)(C + (size_t)m * N + n) = v;
        }
    }
}

// ---------------------------------------------------------------------------
// Persistent RNN layer: r[:,t,:] = tanh(xp[:,t,:] + r[:,t-1,:] @ W_hh^T)
//
// Grid: 128 blocks = 4 batch-groups (8 batches) x 32 col-groups (32 cols).
// Block: 512 threads = 16 warps; warp <-> k-chunk (64 k), lane <-> col.
//
// W_hh slice lives in REGISTERS (32 f32x2 per thread), loaded once through a
// coalesced smem staging pass; smem region is then reused for h + partials.
// Per step crossbar traffic = h broadcasts only (~2048 cyc), balanced with
// the FFMA2 pipe (~2048 cyc).
//
// Inter-block step barrier (per group of 32 blocks): producers store h_t ->
// bar.sync 1,256 -> tid0 atom.add.acq_rel; last arriver st.release's the
// group flag = t+1. Waiters: lane0-per-warp acquire-poll + shfl broadcast
// (128 pollers per flag line), then straight into warp-local staging.
// ---------------------------------------------------------------------------
#define WPAD 1028                      // 1028 % 32 == 4 -> conflict-free LDS.128
#define RNN_BLOCKS 128
#define RNN_SMEM_FLOATS (32 * WPAD)    // 131.6KB: W staging, reused for h/psm;
                                       // also forces 1 block/SM

__global__ __launch_bounds__(512) void rnn_layer_kernel(
    int rsel, const float* __restrict__ W)
{
    float* r = (rsel == SEL_R1) ? g_r1 : g_r2;

    extern __shared__ float sm[];

    const int tid  = threadIdx.x;
    const int warp = tid >> 5;              // k-chunk 0..15
    const int lane = tid & 31;              // col within group
    const int bg = blockIdx.x >> 5;         // 0..3
    const int cg = blockIdx.x & 31;         // 0..31
    const int b0 = bg * 8;
    const int c0 = cg * 32;
    const int kbase = warp * 64;

    unsigned* cnt  = &g_cnt4[bg * 32];
    unsigned* flag = &g_flag4[bg * 32];

    // ---- phase 1: stage W slice coalesced into smem ----
    #pragma unroll
    for (int i = tid; i < 8192; i += 512) {
        const int rr = i >> 8;
        const int q  = (i & 255) << 2;
        *(float4*)&sm[rr * WPAD + q] =
            *(const float4*)(W + (size_t)(c0 + rr) * HH + q);
    }
    __syncthreads();

    // ---- phase 2: my W row-chunk into registers (32 f32x2) ----
    unsigned long long wreg[32];
    {
        const ulonglong2* wsrc = (const ulonglong2*)&sm[lane * WPAD + kbase];
        #pragma unroll
        for (int q = 0; q < 16; q++) {
            ulonglong2 v = wsrc[q];
            wreg[2 * q]     = v.x;
            wreg[2 * q + 1] = v.y;
        }
    }
    __syncthreads();   // everyone done reading W staging; reuse smem

    float* hw  = sm + warp * 512;           // 16 warps x (8 batches x 64 k)
    float* psm = sm + 16 * 512;             // 16 x 8 x 32 partials

    const float* xp_ptr = g_xp + ((size_t)(b0 + warp) * LL) * HH + (c0 + lane);
    float*       r_ptr  = r    + ((size_t)(b0 + warp) * LL) * HH + (c0 + lane);

    for (int t = 0; t < LL; t++) {
        float xq = 0.0f;
        if (t > 0) {
            // wait for h_{t-1}: lane0 acquire-poll, broadcast via shfl
            unsigned f;
            do {
                f = (lane == 0) ? ld_acquire(flag) : 0u;
                f = __shfl_sync(0xffffffffu, f, 0);
            } while (f < (unsigned)t);

            // warp-local h staging: 4 float4 per thread (own k-chunk, 8 rows)
            const float* hsrc = r + (size_t)(t - 1) * HH + kbase;
            #pragma unroll
            for (int j = 0; j < 4; j++) {
                const int i  = j * 32 + lane;
                const int rr = i >> 4;            // 0..7
                const int qq = (i & 15) << 2;     // 0..60
                *(float4*)&hw[rr * 64 + qq] =
                    *(const float4*)(hsrc + (size_t)(b0 + rr) * LL * HH + qq);
            }
            __syncwarp();

            if (warp < 8) xq = __ldg(xp_ptr + (size_t)t * HH);

            unsigned long long acc[8];
            #pragma unroll
            for (int b = 0; b < 8; b++) acc[b] = 0ull;

            #pragma unroll
            for (int q = 0; q < 16; q++) {
                #pragma unroll
                for (int b = 0; b < 8; b++) {
                    const ulonglong2 hv = *(const ulonglong2*)&hw[b * 64 + q * 4];
                    fma2(acc[b], wreg[2 * q],     hv.x);
                    fma2(acc[b], wreg[2 * q + 1], hv.y);
                }
            }

            #pragma unroll
            for (int b = 0; b < 8; b++)
                psm[warp * 256 + b * 32 + lane] = lo32(acc[b]) + hi32(acc[b]);
            __syncthreads();
        } else {
            if (warp < 8) xq = __ldg(xp_ptr);
        }

        // producers: reduce + activation + store + publish
        if (warp < 8) {
            float dot = 0.0f;
            if (t > 0) {
                #pragma unroll
                for (int w = 0; w < 16; w++)
                    dot += psm[w * 256 + warp * 32 + lane];
            }
            r_ptr[(size_t)t * HH] = fast_tanh(xq + dot);

            if (t < LL - 1) {
                asm volatile("bar.sync 1, 256;" ::: "memory");  // warps 0-7
                if (tid == 0) {
                    unsigned old = atom_add_acq_rel(cnt, 1u);
                    if (old == 32u * (unsigned)(t + 1) - 1u)
                        st_release(flag, (unsigned)(t + 1));
                }
            }
        }
        // warps 8-15 fall through to the next iteration's flag poll
    }
}

// reset barrier state (before each rnn layer -> deterministic replays)
__global__ void rnn_init_kernel()
{
    if (threadIdx.x < 4) {
        g_cnt4[threadIdx.x * 32]  = 0u;
        g_flag4[threadIdx.x * 32] = 0u;
    }
}

// ---------------------------------------------------------------------------
// Launch: 8 graph nodes
// ---------------------------------------------------------------------------
extern "C" void kernel_launch(void* const* d_in, const int* in_sizes, int n_in,
                              void* d_out, int out_size)
{
    const float* x     = (const float*)d_in[0];
    const float* W_ih1 = (const float*)d_in[1];
    const float* W_hh1 = (const float*)d_in[2];
    const float* b_ih1 = (const float*)d_in[3];
    const float* b_hh1 = (const float*)d_in[4];
    const float* W_ih2 = (const float*)d_in[5];
    const float* W_hh2 = (const float*)d_in[6];
    const float* b_ih2 = (const float*)d_in[7];
    const float* b_hh2 = (const float*)d_in[8];
    const float* W1    = (const float*)d_in[9];
    const float* b1    = (const float*)d_in[10];
    const float* W2    = (const float*)d_in[11];
    const float* b2    = (const float*)d_in[12];
    float* out = (float*)d_out;

    static int smem_set = 0;
    if (!smem_set) {
        cudaFuncSetAttribute(rnn_layer_kernel,
                             cudaFuncAttributeMaxDynamicSharedMemorySize,
                             RNN_SMEM_FLOATS * sizeof(float));
        smem_set = 1;
    }
    const size_t rnn_smem = RNN_SMEM_FLOATS * sizeof(float);

    const dim3 gBig(HH / BN, BL / BM);   // (8, 128)
    const dim3 gOut(OO / BN, BL / BM);   // (1, 128)

    sgemm_bias<<<gBig, 256>>>(x, SEL_EXT, W_ih1, nullptr, SEL_XP,
                              b_ih1, b_hh1, BL, HH, EE);
    rnn_init_kernel<<<1, 32>>>();
    rnn_layer_kernel<<<RNN_BLOCKS, 512, rnn_smem>>>(SEL_R1, W_hh1);

    sgemm_bias<<<gBig, 256>>>(nullptr, SEL_R1, W_ih2, nullptr, SEL_XP,
                              b_ih2, b_hh2, BL, HH, HH);
    rnn_init_kernel<<<1, 32>>>();
    rnn_layer_kernel<<<RNN_BLOCKS, 512, rnn_smem>>>(SEL_R2, W_hh2);

    sgemm_bias<<<gOut, 256>>>(nullptr, SEL_R1, W1, out, SEL_EXT,
                              b1, nullptr, BL, OO, HH);
    sgemm_bias<<<gOut, 256>>>(nullptr, SEL_R2, W2, out + (size_t)BL * OO, SEL_EXT,
                              b2, nullptr, BL, OO, HH);
}

// round 8
// speedup vs baseline: 1.2344x; 1.1066x over previous
#include <cuda_runtime.h>
#include <math.h>

// Problem dims
#define BB   32
#define LL   512
#define EE   768
#define HH   1024
#define OO   128
#define BL   (BB * LL)          // 16384

// ---------------------------------------------------------------------------
// Static scratch (allocation-free)
// ---------------------------------------------------------------------------
__device__ float g_xp[(size_t)BL * HH];
__device__ float g_r1[(size_t)BL * HH];
__device__ float g_r2[(size_t)BL * HH];

// per-block done flags: pair (cg=2p, cg=2p+1) of group bg lives in words 0,1
// of its own 128B line: index = (bg*16 + p)*32 + (cg&1).   4*16 lines.
__device__ unsigned g_done[4 * 16 * 32];

#define SEL_EXT 0
#define SEL_R1  1
#define SEL_R2  2
#define SEL_XP  3

__device__ __forceinline__ const float* pick_src(int sel, const float* ext) {
    if (sel == SEL_R1) return g_r1;
    if (sel == SEL_R2) return g_r2;
    if (sel == SEL_XP) return g_xp;
    return ext;
}
__device__ __forceinline__ float* pick_dst(int sel, float* ext) {
    if (sel == SEL_XP) return g_xp;
    if (sel == SEL_R1) return g_r1;
    if (sel == SEL_R2) return g_r2;
    return ext;
}

// packed f32x2 fma: acc = a*b + acc
__device__ __forceinline__ void fma2(unsigned long long& acc,
                                     unsigned long long a,
                                     unsigned long long b) {
    asm("fma.rn.f32x2 %0, %1, %2, %0;" : "+l"(acc) : "l"(a), "l"(b));
}
__device__ __forceinline__ float lo32(unsigned long long v) {
    return __uint_as_float((unsigned)v);
}
__device__ __forceinline__ float hi32(unsigned long long v) {
    return __uint_as_float((unsigned)(v >> 32));
}

// fast tanh via MUFU: tanh(x) = 1 - 2/(e^{2x}+1)
__device__ __forceinline__ float fast_tanh(float x) {
    float xc = fminf(fmaxf(x, -15.0f), 15.0f);
    float e  = __expf(2.0f * xc);
    return 1.0f - __fdividef(2.0f, e + 1.0f);
}

// release/acquire primitives
__device__ __forceinline__ void st_release(unsigned* p, unsigned v) {
    asm volatile("st.global.release.gpu.u32 [%0], %1;"
                 :: "l"(p), "r"(v) : "memory");
}
__device__ __forceinline__ unsigned ld_acquire(const unsigned* p) {
    unsigned v;
    asm volatile("ld.global.acquire.gpu.u32 %0, [%1];"
                 : "=r"(v) : "l"(p) : "memory");
    return v;
}

// ---------------------------------------------------------------------------
// SGEMM: C[M,N] = A[M,K] * W[N,K]^T + bias1[n] (+ bias2[n])
// 128x128 tile, BK=8, 256 threads, 8x8/thread, f32x2 FMA, double-buffered.
// ---------------------------------------------------------------------------
#define BM 128
#define BN 128
#define BK 8

__global__ __launch_bounds__(256) void sgemm_bias(
    const float* __restrict__ Aext, int Asel,
    const float* __restrict__ W,
    float* __restrict__ Cext, int Csel,
    const float* __restrict__ bias1, const float* __restrict__ bias2,
    int M, int N, int K)
{
    const float* A = pick_src(Asel, Aext);
    float* C = pick_dst(Csel, Cext);

    __shared__ float As[2][BK][BM];
    __shared__ float Bs[2][BK][BN];

    const int tid = threadIdx.x;
    const int tx = tid & 15;
    const int ty = tid >> 4;
    const int m0 = blockIdx.y * BM;
    const int n0 = blockIdx.x * BN;

    const int la_r = tid >> 1;
    const int la_k = (tid & 1) * 4;

    unsigned long long acc[8][4];
    #pragma unroll
    for (int i = 0; i < 8; i++)
        #pragma unroll
        for (int j = 0; j < 4; j++) acc[i][j] = 0ull;

    float4 av = *(const float4*)(A + (size_t)(m0 + la_r) * K + la_k);
    float4 bv = *(const float4*)(W + (size_t)(n0 + la_r) * K + la_k);

    int buf = 0;
    for (int k0 = 0; k0 < K; k0 += BK) {
        As[buf][la_k + 0][la_r] = av.x; As[buf][la_k + 1][la_r] = av.y;
        As[buf][la_k + 2][la_r] = av.z; As[buf][la_k + 3][la_r] = av.w;
        Bs[buf][la_k + 0][la_r] = bv.x; Bs[buf][la_k + 1][la_r] = bv.y;
        Bs[buf][la_k + 2][la_r] = bv.z; Bs[buf][la_k + 3][la_r] = bv.w;
        __syncthreads();

        if (k0 + BK < K) {
            av = *(const float4*)(A + (size_t)(m0 + la_r) * K + k0 + BK + la_k);
            bv = *(const float4*)(W + (size_t)(n0 + la_r) * K + k0 + BK + la_k);
        }

        #pragma unroll
        for (int kk = 0; kk < BK; kk++) {
            float a[8];
            *(float4*)(a)     = *(const float4*)&As[buf][kk][ty * 4];
            *(float4*)(a + 4) = *(const float4*)&As[buf][kk][ty * 4 + 64];
            ulonglong2 bv0 = *(const ulonglong2*)&Bs[buf][kk][tx * 4];
            ulonglong2 bv1 = *(const ulonglong2*)&Bs[buf][kk][tx * 4 + 64];
            unsigned long long bp[4] = {bv0.x, bv0.y, bv1.x, bv1.y};
            #pragma unroll
            for (int i = 0; i < 8; i++) {
                unsigned long long ap;
                unsigned ai = __float_as_uint(a[i]);
                asm("mov.b64 %0, {%1, %1};" : "=l"(ap) : "r"(ai));
                #pragma unroll
                for (int jp = 0; jp < 4; jp++)
                    fma2(acc[i][jp], ap, bp[jp]);
            }
        }
        buf ^= 1;
    }

    #pragma unroll
    for (int jg = 0; jg < 2; jg++) {
        const int n = n0 + tx * 4 + jg * 64;
        float4 bb = make_float4(0.f, 0.f, 0.f, 0.f);
        if (bias1) {
            float4 t = *(const float4*)(bias1 + n);
            bb.x += t.x; bb.y += t.y; bb.z += t.z; bb.w += t.w;
        }
        if (bias2) {
            float4 t = *(const float4*)(bias2 + n);
            bb.x += t.x; bb.y += t.y; bb.z += t.z; bb.w += t.w;
        }
        #pragma unroll
        for (int i = 0; i < 8; i++) {
            const int ml = (i < 4) ? (ty * 4 + i) : (64 + ty * 4 + i - 4);
            const int m  = m0 + ml;
            unsigned long long p0 = acc[i][jg * 2 + 0];
            unsigned long long p1 = acc[i][jg * 2 + 1];
            float4 v;
            v.x = lo32(p0) + bb.x;
            v.y = hi32(p0) + bb.y;
            v.z = lo32(p1) + bb.z;
            v.w = hi32(p1) + bb.w;
            *(float4*)(C + (size_t)m * N + n) = v;
        }
    }
}

// ---------------------------------------------------------------------------
// Persistent RNN layer: r[:,t,:] = tanh(xp[:,t,:] + r[:,t-1,:] @ W_hh^T)
//
// Grid: 128 blocks = 4 batch-groups (8 batches) x 32 col-groups (32 cols).
// Block: 512 threads = 16 warps; warp <-> k-chunk (64 k), lane <-> col.
// W_hh slice in REGISTERS (32 f32x2/thread); smem only for h + partials.
//
// Point-to-point step dependency (NO group convergence):
//   block (bg,cg) stores its h_t slice -> bar.sync 1,256 among producers ->
//   tid0 st.release done[bg][cg] = t+1.
//   Consumer warp w (k-chunk, cols 64w..64w+63) depends ONLY on producer
//   blocks cg = 2w, 2w+1 of its own group: lanes 0-1 acquire-poll the flag
//   pair (one 128B line, one coalesced request), min via shfl, then stage
//   warp-locally. 32 pollers per line; no atomics anywhere.
// ---------------------------------------------------------------------------
#define WPAD 1028                      // 1028 % 32 == 4 -> conflict-free LDS.128
#define RNN_BLOCKS 128
#define RNN_SMEM_FLOATS (32 * WPAD)    // 131.6KB W staging (reused); 1 block/SM

__global__ __launch_bounds__(512) void rnn_layer_kernel(
    int rsel, const float* __restrict__ W)
{
    float* r = (rsel == SEL_R1) ? g_r1 : g_r2;

    extern __shared__ float sm[];

    const int tid  = threadIdx.x;
    const int warp = tid >> 5;              // k-chunk 0..15
    const int lane = tid & 31;              // col within group
    const int bg = blockIdx.x >> 5;         // 0..3
    const int cg = blockIdx.x & 31;         // 0..31
    const int b0 = bg * 8;
    const int c0 = cg * 32;
    const int kbase = warp * 64;

    // my publish slot; my poll line (flags for col-groups 2*warp, 2*warp+1)
    unsigned* my_flag   = &g_done[(bg * 16 + (cg >> 1)) * 32 + (cg & 1)];
    unsigned* poll_line = &g_done[(bg * 16 + warp) * 32];

    // ---- phase 1: stage W slice coalesced into smem ----
    #pragma unroll
    for (int i = tid; i < 8192; i += 512) {
        const int rr = i >> 8;
        const int q  = (i & 255) << 2;
        *(float4*)&sm[rr * WPAD + q] =
            *(const float4*)(W + (size_t)(c0 + rr) * HH + q);
    }
    __syncthreads();

    // ---- phase 2: my W row-chunk into registers (32 f32x2) ----
    unsigned long long wreg[32];
    {
        const ulonglong2* wsrc = (const ulonglong2*)&sm[lane * WPAD + kbase];
        #pragma unroll
        for (int q = 0; q < 16; q++) {
            ulonglong2 v = wsrc[q];
            wreg[2 * q]     = v.x;
            wreg[2 * q + 1] = v.y;
        }
    }
    __syncthreads();   // done reading W staging; reuse smem

    float* hw  = sm + warp * 512;           // 16 warps x (8 batches x 64 k)
    float* psm = sm + 16 * 512;             // 16 x 8 x 32 partials

    const float* xp_ptr = g_xp + ((size_t)(b0 + warp) * LL) * HH + (c0 + lane);
    float*       r_ptr  = r    + ((size_t)(b0 + warp) * LL) * HH + (c0 + lane);

    for (int t = 0; t < LL; t++) {
        float xq = 0.0f;
        if (t > 0) {
            // wait for my TWO producer blocks only (lanes 0-1 read the pair)
            unsigned f;
            do {
                unsigned v = (lane < 2) ? ld_acquire(poll_line + lane) : 0u;
                unsigned f0 = __shfl_sync(0xffffffffu, v, 0);
                unsigned f1 = __shfl_sync(0xffffffffu, v, 1);
                f = (f0 < f1) ? f0 : f1;
            } while (f < (unsigned)t);

            // warp-local h staging: 4 float4 per thread (own k-chunk, 8 rows)
            const float* hsrc = r + (size_t)(t - 1) * HH + kbase;
            #pragma unroll
            for (int j = 0; j < 4; j++) {
                const int i  = j * 32 + lane;
                const int rr = i >> 4;            // 0..7
                const int qq = (i & 15) << 2;     // 0..60
                *(float4*)&hw[rr * 64 + qq] =
                    *(const float4*)(hsrc + (size_t)(b0 + rr) * LL * HH + qq);
            }
            __syncwarp();

            if (warp < 8) xq = __ldg(xp_ptr + (size_t)t * HH);

            unsigned long long acc[8];
            #pragma unroll
            for (int b = 0; b < 8; b++) acc[b] = 0ull;

            #pragma unroll
            for (int q = 0; q < 16; q++) {
                #pragma unroll
                for (int b = 0; b < 8; b++) {
                    const ulonglong2 hv = *(const ulonglong2*)&hw[b * 64 + q * 4];
                    fma2(acc[b], wreg[2 * q],     hv.x);
                    fma2(acc[b], wreg[2 * q + 1], hv.y);
                }
            }

            #pragma unroll
            for (int b = 0; b < 8; b++)
                psm[warp * 256 + b * 32 + lane] = lo32(acc[b]) + hi32(acc[b]);
            __syncthreads();
        } else {
            if (warp < 8) xq = __ldg(xp_ptr);
        }

        // producers: reduce + activation + store + publish
        if (warp < 8) {
            float dot = 0.0f;
            if (t > 0) {
                #pragma unroll
                for (int w = 0; w < 16; w++)
                    dot += psm[w * 256 + warp * 32 + lane];
            }
            r_ptr[(size_t)t * HH] = fast_tanh(xq + dot);

            if (t < LL - 1) {
                asm volatile("bar.sync 1, 256;" ::: "memory");  // warps 0-7
                if (tid == 0)
                    st_release(my_flag, (unsigned)(t + 1));
            }
        }
        // warps 8-15 fall through to the next iteration's flag poll
    }
}

// reset done flags (before each rnn layer -> deterministic replays)
__global__ void rnn_init_kernel()
{
    const int i = threadIdx.x;          // 0..127 -> (bg*16+p, word)
    if (i < 128) g_done[(i >> 1) * 32 + (i & 1)] = 0u;
}

// ---------------------------------------------------------------------------
// Launch: 8 graph nodes
// ---------------------------------------------------------------------------
extern "C" void kernel_launch(void* const* d_in, const int* in_sizes, int n_in,
                              void* d_out, int out_size)
{
    const float* x     = (const float*)d_in[0];
    const float* W_ih1 = (const float*)d_in[1];
    const float* W_hh1 = (const float*)d_in[2];
    const float* b_ih1 = (const float*)d_in[3];
    const float* b_hh1 = (const float*)d_in[4];
    const float* W_ih2 = (const float*)d_in[5];
    const float* W_hh2 = (const float*)d_in[6];
    const float* b_ih2 = (const float*)d_in[7];
    const float* b_hh2 = (const float*)d_in[8];
    const float* W1    = (const float*)d_in[9];
    const float* b1    = (const float*)d_in[10];
    const float* W2    = (const float*)d_in[11];
    const float* b2    = (const float*)d_in[12];
    float* out = (float*)d_out;

    static int smem_set = 0;
    if (!smem_set) {
        cudaFuncSetAttribute(rnn_layer_kernel,
                             cudaFuncAttributeMaxDynamicSharedMemorySize,
                             RNN_SMEM_FLOATS * sizeof(float));
        smem_set = 1;
    }
    const size_t rnn_smem = RNN_SMEM_FLOATS * sizeof(float);

    const dim3 gBig(HH / BN, BL / BM);   // (8, 128)
    const dim3 gOut(OO / BN, BL / BM);   // (1, 128)

    sgemm_bias<<<gBig, 256>>>(x, SEL_EXT, W_ih1, nullptr, SEL_XP,
                              b_ih1, b_hh1, BL, HH, EE);
    rnn_init_kernel<<<1, 128>>>();
    rnn_layer_kernel<<<RNN_BLOCKS, 512, rnn_smem>>>(SEL_R1, W_hh1);

    sgemm_bias<<<gBig, 256>>>(nullptr, SEL_R1, W_ih2, nullptr, SEL_XP,
                              b_ih2, b_hh2, BL, HH, HH);
    rnn_init_kernel<<<1, 128>>>();
    rnn_layer_kernel<<<RNN_BLOCKS, 512, rnn_smem>>>(SEL_R2, W_hh2);

    sgemm_bias<<<gOut, 256>>>(nullptr, SEL_R1, W1, out, SEL_EXT,
                              b1, nullptr, BL, OO, HH);
    sgemm_bias<<<gOut, 256>>>(nullptr, SEL_R2, W2, out + (size_t)BL * OO, SEL_EXT,
                              b2, nullptr, BL, OO, HH);
}

// round 11
// speedup vs baseline: 1.3761x; 1.1148x over previous
#include <cuda_runtime.h>
#include <cuda_bf16.h>
#include <math.h>
#include <stdint.h>

// Problem dims
#define BB   32
#define LL   512
#define EE   768
#define HH   1024
#define OO   128
#define BL   (BB * LL)          // 16384

// ---------------------------------------------------------------------------
// Static scratch (allocation-free) — same footprint as the R8-passing kernel
// ---------------------------------------------------------------------------
__device__ float g_xp[(size_t)BL * HH];
__device__ float g_r1[(size_t)BL * HH];
__device__ float g_r2[(size_t)BL * HH];

// per-block done flags (R8 layout)
__device__ unsigned g_done[4 * 16 * 32];

#define SEL_EXT 0
#define SEL_R1  1
#define SEL_R2  2
#define SEL_XP  3

__device__ __forceinline__ const float* pick_src(int sel, const float* ext) {
    if (sel == SEL_R1) return g_r1;
    if (sel == SEL_R2) return g_r2;
    if (sel == SEL_XP) return g_xp;
    return ext;
}
__device__ __forceinline__ float* pick_dst(int sel, float* ext) {
    if (sel == SEL_XP) return g_xp;
    if (sel == SEL_R1) return g_r1;
    if (sel == SEL_R2) return g_r2;
    return ext;
}

// ---------------------------------------------------------------------------
// helpers
// ---------------------------------------------------------------------------
__device__ __forceinline__ uint32_t smem_to_u32(const void* p) {
    uint32_t a;
    asm("{ .reg .u64 t; cvta.to.shared.u64 t, %1; cvt.u32.u64 %0, t; }"
        : "=r"(a) : "l"(p));
    return a;
}
__device__ __forceinline__ void fma2(unsigned long long& acc,
                                     unsigned long long a,
                                     unsigned long long b) {
    asm("fma.rn.f32x2 %0, %1, %2, %0;" : "+l"(acc) : "l"(a), "l"(b));
}
__device__ __forceinline__ float lo32(unsigned long long v) {
    return __uint_as_float((unsigned)v);
}
__device__ __forceinline__ float hi32(unsigned long long v) {
    return __uint_as_float((unsigned)(v >> 32));
}
__device__ __forceinline__ float fast_tanh(float x) {
    float xc = fminf(fmaxf(x, -15.0f), 15.0f);
    float e  = __expf(2.0f * xc);
    return 1.0f - __fdividef(2.0f, e + 1.0f);
}
__device__ __forceinline__ void st_release(unsigned* p, unsigned v) {
    asm volatile("st.global.release.gpu.u32 [%0], %1;" :: "l"(p), "r"(v) : "memory");
}
__device__ __forceinline__ unsigned ld_acquire(const unsigned* p) {
    unsigned v;
    asm volatile("ld.global.acquire.gpu.u32 %0, [%1];" : "=r"(v) : "l"(p) : "memory");
    return v;
}

// ldmatrix / mma.sync (sm_80-baseline ISA)
#define LDSM4(r, a) \
    asm volatile("ldmatrix.sync.aligned.m8n8.x4.shared.b16 {%0,%1,%2,%3}, [%4];" \
        : "=r"((r)[0]), "=r"((r)[1]), "=r"((r)[2]), "=r"((r)[3]) : "r"(a))
#define LDSM2(r, a) \
    asm volatile("ldmatrix.sync.aligned.m8n8.x2.shared.b16 {%0,%1}, [%2];" \
        : "=r"((r)[0]), "=r"((r)[1]) : "r"(a))
#define MMA16816(d, a, b) \
    asm volatile("mma.sync.aligned.m16n8k16.row.col.f32.bf16.bf16.f32 " \
        "{%0,%1,%2,%3}, {%4,%5,%6,%7}, {%8,%9}, {%0,%1,%2,%3};" \
        : "+f"((d)[0]), "+f"((d)[1]), "+f"((d)[2]), "+f"((d)[3]) \
        : "r"((a)[0]), "r"((a)[1]), "r"((a)[2]), "r"((a)[3]), \
          "r"((b)[0]), "r"((b)[1]))

// 8 fp32 -> 8 bf16 hi (uint4) + 8 bf16 lo (uint4)
__device__ __forceinline__ void split8(const float4 v0, const float4 v1,
                                       uint4& hh, uint4& ll)
{
    float f[8] = {v0.x, v0.y, v0.z, v0.w, v1.x, v1.y, v1.z, v1.w};
    __nv_bfloat162 h[4], l[4];
    #pragma unroll
    for (int i = 0; i < 4; i++) {
        __nv_bfloat16 h0 = __float2bfloat16(f[2*i]);
        __nv_bfloat16 h1 = __float2bfloat16(f[2*i+1]);
        h[i] = __nv_bfloat162(h0, h1);
        l[i] = __nv_bfloat162(__float2bfloat16(f[2*i]   - __bfloat162float(h0)),
                              __float2bfloat16(f[2*i+1] - __bfloat162float(h1)));
    }
    hh = *(uint4*)h;
    ll = *(uint4*)l;
}

// ---------------------------------------------------------------------------
// HMMA GEMM: C[M,Nfull] = A[M,K] @ B[Nfull,K]^T + bias1 (+bias2), fp32 in/out.
// A,B converted to bf16 hi/lo IN-KERNEL during smem staging (no global split
// buffers). 3-pass hi/lo: AhBh + AhBl + AlBh, fp32 accumulators.
// 128x128 C tile, 256 threads = 8 warps (2m x 4n), warp tile 64x32
// = 4x4 m16n8k16 fragments. K-chunk 32; smem rows padded to 40 bf16.
// Inner loops restructured so live fragments stay small (no spills).
// ---------------------------------------------------------------------------
#define GKC  32
#define GPAD 40

__global__ __launch_bounds__(256) void mma_gemm(
    const float* __restrict__ Aext, int Asel,
    const float* __restrict__ B,            // external fp32 [Nfull,K]
    float* __restrict__ Cext, int Csel,
    const float* __restrict__ bias1, const float* __restrict__ bias2,
    int Nfull, int K)
{
    const float* A = pick_src(Asel, Aext);
    float* C = pick_dst(Csel, Cext);

    __shared__ __nv_bfloat16 sAh[128 * GPAD], sAl[128 * GPAD];
    __shared__ __nv_bfloat16 sBh[128 * GPAD], sBl[128 * GPAD];

    const int tid  = threadIdx.x;
    const int wid  = tid >> 5;
    const int lane = tid & 31;
    const int wm   = wid >> 2;            // 0..1
    const int wn   = wid & 3;             // 0..3
    const int m0   = blockIdx.y * 128;
    const int n0   = blockIdx.x * 128;

    float acc[4][4][4];
    #pragma unroll
    for (int i = 0; i < 4; i++)
        #pragma unroll
        for (int j = 0; j < 4; j++)
            #pragma unroll
            for (int k = 0; k < 4; k++) acc[i][j][k] = 0.0f;

    const uint32_t uAh = smem_to_u32(sAh), uAl = smem_to_u32(sAl);
    const uint32_t uBh = smem_to_u32(sBh), uBl = smem_to_u32(sBl);
    // A frag addr: rows (lane&15), k-half (lane>>4)*8 elems
    const uint32_t aoff = (uint32_t)((wm * 64 + (lane & 15)) * GPAD + (lane >> 4) * 8) * 2u;
    // B frag addr: n-rows (lane&7), k-half ((lane>>3)&1)*8 elems
    const uint32_t boff = (uint32_t)((wn * 32 + (lane & 7)) * GPAD + ((lane >> 3) & 1) * 8) * 2u;

    for (int k0 = 0; k0 < K; k0 += GKC) {
        // stage + split: 512 8-float chunks for A, 512 for B; 4 per thread.
        // p=0,1 -> A (i<512), p=2,3 -> B : uniform per unrolled p.
        #pragma unroll
        for (int p = 0; p < 4; p++) {
            const int i   = p * 256 + tid;
            const int j   = i & 511;
            const int row = j >> 2;              // 0..127
            const int seg = j & 3;               // 8-float segment
            const int so  = row * GPAD + seg * 8;
            if (p < 2) {
                const float* src = A + (size_t)(m0 + row) * K + k0 + seg * 8;
                float4 v0 = *(const float4*)src;
                float4 v1 = *(const float4*)(src + 4);
                uint4 hh, ll;
                split8(v0, v1, hh, ll);
                *(uint4*)&sAh[so] = hh;
                *(uint4*)&sAl[so] = ll;
            } else {
                const float* src = B + (size_t)(n0 + row) * K + k0 + seg * 8;
                float4 v0 = *(const float4*)src;
                float4 v1 = *(const float4*)(src + 4);
                uint4 hh, ll;
                split8(v0, v1, hh, ll);
                *(uint4*)&sBh[so] = hh;
                *(uint4*)&sBl[so] = ll;
            }
        }
        __syncthreads();

        #pragma unroll
        for (int ks = 0; ks < 2; ks++) {
            const uint32_t ko = (uint32_t)(ks * 16) * 2u;   // byte offset
            uint32_t bh[4][2], bl[4][2];
            #pragma unroll
            for (int nf = 0; nf < 4; nf++) {
                const uint32_t fo = (uint32_t)(nf * 8 * GPAD) * 2u + ko;
                LDSM2(bh[nf], uBh + boff + fo);
                LDSM2(bl[nf], uBl + boff + fo);
            }
            #pragma unroll
            for (int mf = 0; mf < 4; mf++) {
                const uint32_t fo = (uint32_t)(mf * 16 * GPAD) * 2u + ko;
                uint32_t ah[4], al[4];
                LDSM4(ah, uAh + aoff + fo);
                LDSM4(al, uAl + aoff + fo);
                #pragma unroll
                for (int nf = 0; nf < 4; nf++) {
                    MMA16816(acc[mf][nf], ah, bh[nf]);
                    MMA16816(acc[mf][nf], ah, bl[nf]);
                    MMA16816(acc[mf][nf], al, bh[nf]);
                }
            }
        }
        __syncthreads();
    }

    // epilogue: c0,c1 -> (row = lane/4, col = 2*(lane%4)); c2,c3 -> row+8
    #pragma unroll
    for (int mf = 0; mf < 4; mf++) {
        const int mrow = m0 + wm * 64 + mf * 16 + (lane >> 2);
        #pragma unroll
        for (int nf = 0; nf < 4; nf++) {
            const int col = n0 + wn * 32 + nf * 8 + (lane & 3) * 2;
            float b0 = bias1[col], b1 = bias1[col + 1];
            if (bias2) { b0 += bias2[col]; b1 += bias2[col + 1]; }
            float2 v0 = make_float2(acc[mf][nf][0] + b0, acc[mf][nf][1] + b1);
            float2 v1 = make_float2(acc[mf][nf][2] + b0, acc[mf][nf][3] + b1);
            *(float2*)(C + (size_t)mrow * Nfull + col) = v0;
            *(float2*)(C + (size_t)(mrow + 8) * Nfull + col) = v1;
        }
    }
}

// ---------------------------------------------------------------------------
// Persistent RNN layer (identical to Round-8 passing version)
// ---------------------------------------------------------------------------
#define WPAD 1028
#define RNN_BLOCKS 128
#define RNN_SMEM_FLOATS (32 * WPAD)

__global__ __launch_bounds__(512) void rnn_layer_kernel(
    int rsel, const float* __restrict__ W)
{
    float* r = (rsel == SEL_R1) ? g_r1 : g_r2;

    extern __shared__ float sm[];

    const int tid  = threadIdx.x;
    const int warp = tid >> 5;
    const int lane = tid & 31;
    const int bg = blockIdx.x >> 5;
    const int cg = blockIdx.x & 31;
    const int b0 = bg * 8;
    const int c0 = cg * 32;
    const int kbase = warp * 64;

    unsigned* my_flag   = &g_done[(bg * 16 + (cg >> 1)) * 32 + (cg & 1)];
    unsigned* poll_line = &g_done[(bg * 16 + warp) * 32];

    #pragma unroll
    for (int i = tid; i < 8192; i += 512) {
        const int rr = i >> 8;
        const int q  = (i & 255) << 2;
        *(float4*)&sm[rr * WPAD + q] =
            *(const float4*)(W + (size_t)(c0 + rr) * HH + q);
    }
    __syncthreads();

    unsigned long long wreg[32];
    {
        const ulonglong2* wsrc = (const ulonglong2*)&sm[lane * WPAD + kbase];
        #pragma unroll
        for (int q = 0; q < 16; q++) {
            ulonglong2 v = wsrc[q];
            wreg[2 * q]     = v.x;
            wreg[2 * q + 1] = v.y;
        }
    }
    __syncthreads();

    float* hw  = sm + warp * 512;
    float* psm = sm + 16 * 512;

    const float* xp_ptr = g_xp + ((size_t)(b0 + warp) * LL) * HH + (c0 + lane);
    float*       r_ptr  = r    + ((size_t)(b0 + warp) * LL) * HH + (c0 + lane);

    for (int t = 0; t < LL; t++) {
        float xq = 0.0f;
        if (t > 0) {
            unsigned f;
            do {
                unsigned v = (lane < 2) ? ld_acquire(poll_line + lane) : 0u;
                unsigned f0 = __shfl_sync(0xffffffffu, v, 0);
                unsigned f1 = __shfl_sync(0xffffffffu, v, 1);
                f = (f0 < f1) ? f0 : f1;
            } while (f < (unsigned)t);

            const float* hsrc = r + (size_t)(t - 1) * HH + kbase;
            #pragma unroll
            for (int j = 0; j < 4; j++) {
                const int i  = j * 32 + lane;
                const int rr = i >> 4;
                const int qq = (i & 15) << 2;
                *(float4*)&hw[rr * 64 + qq] =
                    *(const float4*)(hsrc + (size_t)(b0 + rr) * LL * HH + qq);
            }
            __syncwarp();

            if (warp < 8) xq = __ldg(xp_ptr + (size_t)t * HH);

            unsigned long long acc[8];
            #pragma unroll
            for (int b = 0; b < 8; b++) acc[b] = 0ull;

            #pragma unroll
            for (int q = 0; q < 16; q++) {
                #pragma unroll
                for (int b = 0; b < 8; b++) {
                    const ulonglong2 hv = *(const ulonglong2*)&hw[b * 64 + q * 4];
                    fma2(acc[b], wreg[2 * q],     hv.x);
                    fma2(acc[b], wreg[2 * q + 1], hv.y);
                }
            }

            #pragma unroll
            for (int b = 0; b < 8; b++)
                psm[warp * 256 + b * 32 + lane] = lo32(acc[b]) + hi32(acc[b]);
            __syncthreads();
        } else {
            if (warp < 8) xq = __ldg(xp_ptr);
        }

        if (warp < 8) {
            float dot = 0.0f;
            if (t > 0) {
                #pragma unroll
                for (int w = 0; w < 16; w++)
                    dot += psm[w * 256 + warp * 32 + lane];
            }
            r_ptr[(size_t)t * HH] = fast_tanh(xq + dot);

            if (t < LL - 1) {
                asm volatile("bar.sync 1, 256;" ::: "memory");
                if (tid == 0)
                    st_release(my_flag, (unsigned)(t + 1));
            }
        }
    }
}

__global__ void rnn_init_kernel()
{
    const int i = threadIdx.x;
    if (i < 128) g_done[(i >> 1) * 32 + (i & 1)] = 0u;
}

// ---------------------------------------------------------------------------
// Launch: 8 graph nodes
// ---------------------------------------------------------------------------
extern "C" void kernel_launch(void* const* d_in, const int* in_sizes, int n_in,
                              void* d_out, int out_size)
{
    const float* x     = (const float*)d_in[0];
    const float* W_ih1 = (const float*)d_in[1];
    const float* W_hh1 = (const float*)d_in[2];
    const float* b_ih1 = (const float*)d_in[3];
    const float* b_hh1 = (const float*)d_in[4];
    const float* W_ih2 = (const float*)d_in[5];
    const float* W_hh2 = (const float*)d_in[6];
    const float* b_ih2 = (const float*)d_in[7];
    const float* b_hh2 = (const float*)d_in[8];
    const float* W1    = (const float*)d_in[9];
    const float* b1    = (const float*)d_in[10];
    const float* W2    = (const float*)d_in[11];
    const float* b2    = (const float*)d_in[12];
    float* out = (float*)d_out;

    static int attr_set = 0;
    if (!attr_set) {
        cudaFuncSetAttribute(rnn_layer_kernel,
                             cudaFuncAttributeMaxDynamicSharedMemorySize,
                             RNN_SMEM_FLOATS * sizeof(float));
        attr_set = 1;
    }
    const size_t rnn_smem = RNN_SMEM_FLOATS * sizeof(float);

    const dim3 gBig(HH / 128, BL / 128);   // (8, 128)
    const dim3 gOut(OO / 128, BL / 128);   // (1, 128)

    // xp = x @ W_ih1^T + b_ih1 + b_hh1
    mma_gemm<<<gBig, 256>>>(x, SEL_EXT, W_ih1,
                            nullptr, SEL_XP, b_ih1, b_hh1, HH, EE);
    // layer 1 recurrence
    rnn_init_kernel<<<1, 128>>>();
    rnn_layer_kernel<<<RNN_BLOCKS, 512, rnn_smem>>>(SEL_R1, W_hh1);

    // xp = r1 @ W_ih2^T + b_ih2 + b_hh2
    mma_gemm<<<gBig, 256>>>(nullptr, SEL_R1, W_ih2,
                            nullptr, SEL_XP, b_ih2, b_hh2, HH, HH);
    // layer 2 recurrence
    rnn_init_kernel<<<1, 128>>>();
    rnn_layer_kernel<<<RNN_BLOCKS, 512, rnn_smem>>>(SEL_R2, W_hh2);

    // y = r1 @ W1^T + b1 ; z = r2 @ W2^T + b2
    mma_gemm<<<gOut, 256>>>(nullptr, SEL_R1, W1,
                            out, SEL_EXT, b1, nullptr, OO, HH);
    mma_gemm<<<gOut, 256>>>(nullptr, SEL_R2, W2,
                            out + (size_t)BL * OO, SEL_EXT, b2, nullptr, OO, HH);
}

// round 13
// speedup vs baseline: 1.7385x; 1.2633x over previous
#include <cuda_runtime.h>
#include <cuda_bf16.h>
#include <math.h>
#include <stdint.h>

// Problem dims
#define BB   32
#define LL   512
#define EE   768
#define HH   1024
#define OO   128
#define BL   (BB * LL)          // 16384

// ---------------------------------------------------------------------------
// Static scratch (allocation-free)
// ---------------------------------------------------------------------------
__device__ float g_xp[(size_t)BL * HH];
__device__ float g_r1[(size_t)BL * HH];
__device__ float g_r2[(size_t)BL * HH];

// per-block done flags (R8 layout)
__device__ unsigned g_done[4 * 16 * 32];

#define SEL_EXT 0
#define SEL_R1  1
#define SEL_R2  2
#define SEL_XP  3

__device__ __forceinline__ const float* pick_src(int sel, const float* ext) {
    if (sel == SEL_R1) return g_r1;
    if (sel == SEL_R2) return g_r2;
    if (sel == SEL_XP) return g_xp;
    return ext;
}
__device__ __forceinline__ float* pick_dst(int sel, float* ext) {
    if (sel == SEL_XP) return g_xp;
    if (sel == SEL_R1) return g_r1;
    if (sel == SEL_R2) return g_r2;
    return ext;
}

// ---------------------------------------------------------------------------
// helpers
// ---------------------------------------------------------------------------
__device__ __forceinline__ uint32_t smem_to_u32(const void* p) {
    uint32_t a;
    asm("{ .reg .u64 t; cvta.to.shared.u64 t, %1; cvt.u32.u64 %0, t; }"
        : "=r"(a) : "l"(p));
    return a;
}
__device__ __forceinline__ float fast_tanh(float x) {
    float xc = fminf(fmaxf(x, -15.0f), 15.0f);
    float e  = __expf(2.0f * xc);
    return 1.0f - __fdividef(2.0f, e + 1.0f);
}
__device__ __forceinline__ void st_release(unsigned* p, unsigned v) {
    asm volatile("st.global.release.gpu.u32 [%0], %1;" :: "l"(p), "r"(v) : "memory");
}
__device__ __forceinline__ unsigned ld_acquire(const unsigned* p) {
    unsigned v;
    asm volatile("ld.global.acquire.gpu.u32 %0, [%1];" : "=r"(v) : "l"(p) : "memory");
    return v;
}

// ldmatrix / mma.sync (sm_80-baseline ISA)
#define LDSM4(r, a) \
    asm volatile("ldmatrix.sync.aligned.m8n8.x4.shared.b16 {%0,%1,%2,%3}, [%4];" \
        : "=r"((r)[0]), "=r"((r)[1]), "=r"((r)[2]), "=r"((r)[3]) : "r"(a))
#define LDSM2(r, a) \
    asm volatile("ldmatrix.sync.aligned.m8n8.x2.shared.b16 {%0,%1}, [%2];" \
        : "=r"((r)[0]), "=r"((r)[1]) : "r"(a))
#define MMA16816(d, a, b) \
    asm volatile("mma.sync.aligned.m16n8k16.row.col.f32.bf16.bf16.f32 " \
        "{%0,%1,%2,%3}, {%4,%5,%6,%7}, {%8,%9}, {%0,%1,%2,%3};" \
        : "+f"((d)[0]), "+f"((d)[1]), "+f"((d)[2]), "+f"((d)[3]) \
        : "r"((a)[0]), "r"((a)[1]), "r"((a)[2]), "r"((a)[3]), \
          "r"((b)[0]), "r"((b)[1]))

// 8 fp32 -> 8 bf16 hi (uint4) + 8 bf16 lo (uint4)
__device__ __forceinline__ void split8(const float4 v0, const float4 v1,
                                       uint4& hh, uint4& ll)
{
    float f[8] = {v0.x, v0.y, v0.z, v0.w, v1.x, v1.y, v1.z, v1.w};
    __nv_bfloat162 h[4], l[4];
    #pragma unroll
    for (int i = 0; i < 4; i++) {
        __nv_bfloat16 h0 = __float2bfloat16(f[2*i]);
        __nv_bfloat16 h1 = __float2bfloat16(f[2*i+1]);
        h[i] = __nv_bfloat162(h0, h1);
        l[i] = __nv_bfloat162(__float2bfloat16(f[2*i]   - __bfloat162float(h0)),
                              __float2bfloat16(f[2*i+1] - __bfloat162float(h1)));
    }
    hh = *(uint4*)h;
    ll = *(uint4*)l;
}

// 4 fp32 -> 4 bf16 hi (uint2) + 4 bf16 lo (uint2)
__device__ __forceinline__ void split4(const float4 v, uint2& hh, uint2& ll)
{
    __nv_bfloat16 h0 = __float2bfloat16(v.x);
    __nv_bfloat16 h1 = __float2bfloat16(v.y);
    __nv_bfloat16 h2 = __float2bfloat16(v.z);
    __nv_bfloat16 h3 = __float2bfloat16(v.w);
    __nv_bfloat162 hp0(h0, h1), hp1(h2, h3);
    __nv_bfloat162 lp0(__float2bfloat16(v.x - __bfloat162float(h0)),
                       __float2bfloat16(v.y - __bfloat162float(h1)));
    __nv_bfloat162 lp1(__float2bfloat16(v.z - __bfloat162float(h2)),
                       __float2bfloat16(v.w - __bfloat162float(h3)));
    hh.x = *(uint32_t*)&hp0; hh.y = *(uint32_t*)&hp1;
    ll.x = *(uint32_t*)&lp0; ll.y = *(uint32_t*)&lp1;
}

// ---------------------------------------------------------------------------
// HMMA GEMM (unchanged from the R11-passing version)
// ---------------------------------------------------------------------------
#define GKC  32
#define GPAD 40

__global__ __launch_bounds__(256) void mma_gemm(
    const float* __restrict__ Aext, int Asel,
    const float* __restrict__ B,
    float* __restrict__ Cext, int Csel,
    const float* __restrict__ bias1, const float* __restrict__ bias2,
    int Nfull, int K)
{
    const float* A = pick_src(Asel, Aext);
    float* C = pick_dst(Csel, Cext);

    __shared__ __nv_bfloat16 sAh[128 * GPAD], sAl[128 * GPAD];
    __shared__ __nv_bfloat16 sBh[128 * GPAD], sBl[128 * GPAD];

    const int tid  = threadIdx.x;
    const int wid  = tid >> 5;
    const int lane = tid & 31;
    const int wm   = wid >> 2;
    const int wn   = wid & 3;
    const int m0   = blockIdx.y * 128;
    const int n0   = blockIdx.x * 128;

    float acc[4][4][4];
    #pragma unroll
    for (int i = 0; i < 4; i++)
        #pragma unroll
        for (int j = 0; j < 4; j++)
            #pragma unroll
            for (int k = 0; k < 4; k++) acc[i][j][k] = 0.0f;

    const uint32_t uAh = smem_to_u32(sAh), uAl = smem_to_u32(sAl);
    const uint32_t uBh = smem_to_u32(sBh), uBl = smem_to_u32(sBl);
    const uint32_t aoff = (uint32_t)((wm * 64 + (lane & 15)) * GPAD + (lane >> 4) * 8) * 2u;
    const uint32_t boff = (uint32_t)((wn * 32 + (lane & 7)) * GPAD + ((lane >> 3) & 1) * 8) * 2u;

    for (int k0 = 0; k0 < K; k0 += GKC) {
        #pragma unroll
        for (int p = 0; p < 4; p++) {
            const int i   = p * 256 + tid;
            const int j   = i & 511;
            const int row = j >> 2;
            const int seg = j & 3;
            const int so  = row * GPAD + seg * 8;
            if (p < 2) {
                const float* src = A + (size_t)(m0 + row) * K + k0 + seg * 8;
                float4 v0 = *(const float4*)src;
                float4 v1 = *(const float4*)(src + 4);
                uint4 hh, ll;
                split8(v0, v1, hh, ll);
                *(uint4*)&sAh[so] = hh;
                *(uint4*)&sAl[so] = ll;
            } else {
                const float* src = B + (size_t)(n0 + row) * K + k0 + seg * 8;
                float4 v0 = *(const float4*)src;
                float4 v1 = *(const float4*)(src + 4);
                uint4 hh, ll;
                split8(v0, v1, hh, ll);
                *(uint4*)&sBh[so] = hh;
                *(uint4*)&sBl[so] = ll;
            }
        }
        __syncthreads();

        #pragma unroll
        for (int ks = 0; ks < 2; ks++) {
            const uint32_t ko = (uint32_t)(ks * 16) * 2u;
            uint32_t bh[4][2], bl[4][2];
            #pragma unroll
            for (int nf = 0; nf < 4; nf++) {
                const uint32_t fo = (uint32_t)(nf * 8 * GPAD) * 2u + ko;
                LDSM2(bh[nf], uBh + boff + fo);
                LDSM2(bl[nf], uBl + boff + fo);
            }
            #pragma unroll
            for (int mf = 0; mf < 4; mf++) {
                const uint32_t fo = (uint32_t)(mf * 16 * GPAD) * 2u + ko;
                uint32_t ah[4], al[4];
                LDSM4(ah, uAh + aoff + fo);
                LDSM4(al, uAl + aoff + fo);
                #pragma unroll
                for (int nf = 0; nf < 4; nf++) {
                    MMA16816(acc[mf][nf], ah, bh[nf]);
                    MMA16816(acc[mf][nf], ah, bl[nf]);
                    MMA16816(acc[mf][nf], al, bh[nf]);
                }
            }
        }
        __syncthreads();
    }

    #pragma unroll
    for (int mf = 0; mf < 4; mf++) {
        const int mrow = m0 + wm * 64 + mf * 16 + (lane >> 2);
        #pragma unroll
        for (int nf = 0; nf < 4; nf++) {
            const int col = n0 + wn * 32 + nf * 8 + (lane & 3) * 2;
            float b0 = bias1[col], b1 = bias1[col + 1];
            if (bias2) { b0 += bias2[col]; b1 += bias2[col + 1]; }
            float2 v0 = make_float2(acc[mf][nf][0] + b0, acc[mf][nf][1] + b1);
            float2 v1 = make_float2(acc[mf][nf][2] + b0, acc[mf][nf][3] + b1);
            *(float2*)(C + (size_t)mrow * Nfull + col) = v0;
            *(float2*)(C + (size_t)(mrow + 8) * Nfull + col) = v1;
        }
    }
}

// ---------------------------------------------------------------------------
// Persistent RNN layer with HMMA inner product.
//
// Grid: 128 blocks = 4 batch-groups (8 batches) x 32 col-groups (32 cols).
// Block: 512 threads = 16 warps; warp <-> k-chunk (64 k).
// W_hh slice held as bf16 hi/lo m16n8k16 A-fragments in REGISTERS,
// built once per layer from an smem image. Per step: h staged fp32 -> bf16
// hi/lo into warp-private smem rows (72-bf16 pad -> conflict-free LDSM2),
// 24 MMAs (3-pass hi/lo), psm partials (stride-9), cross-warp reduce,
// tanh, store, P2P flag publish (identical sync topology to R8/R11).
//
// FIX vs R12: per-warp h staging stride is 2*HW_WARP (hi+lo = 2304 B);
// R12 strode by HW_WARP (1152 B), aliasing warp w's lo onto warp w+1's hi.
// ---------------------------------------------------------------------------
#define RNN_BLOCKS 128
#define RNN_SMEM_BYTES (32 * 1028 * 4)   // 131.6KB -> forces 1 block/SM
#define IMG_PAD 1032                     // bf16 per image row
#define HW_PAD  72                       // bf16 per h row (64 data + 8 pad)
#define HW_WARP (8 * HW_PAD * 2)         // bytes per warp per (hi|lo): 1152
#define PSM_STRIDE 296                   // floats per warp region
#define PSM_OFF 40960                    // byte offset of psm (> 16*2304)

__global__ __launch_bounds__(512) void rnn_layer_kernel(
    int rsel, const float* __restrict__ W)
{
    float* r = (rsel == SEL_R1) ? g_r1 : g_r2;

    extern __shared__ char smc[];

    const int tid  = threadIdx.x;
    const int warp = tid >> 5;
    const int lane = tid & 31;
    const int bg = blockIdx.x >> 5;
    const int cg = blockIdx.x & 31;
    const int b0 = bg * 8;
    const int c0 = cg * 32;
    const int kbase = warp * 64;

    unsigned* my_flag   = &g_done[(bg * 16 + (cg >> 1)) * 32 + (cg & 1)];
    unsigned* poll_line = &g_done[(bg * 16 + warp) * 32];

    // ---- build W_hh bf16 hi/lo fragments in registers (once per layer) ----
    uint32_t wh[2][4][4], wl[2][4][4];
    {
        __nv_bfloat16* img_h = (__nv_bfloat16*)smc;
        __nv_bfloat16* img_l = (__nv_bfloat16*)(smc + 16 * IMG_PAD * 2);
        const uint32_t uih = smem_to_u32(img_h);
        const uint32_t uil = smem_to_u32(img_l);

        #pragma unroll
        for (int mf = 0; mf < 2; mf++) {
            // fill image: rows = 16 cols of W, 1024 k; thread -> (row, 32 k)
            const int row = tid >> 5;            // 0..15
            const int kk0 = (tid & 31) * 32;
            const float* wsrc = W + (size_t)(c0 + mf * 16 + row) * HH + kk0;
            #pragma unroll
            for (int j = 0; j < 8; j++) {
                float4 v = *(const float4*)(wsrc + j * 4);
                uint2 hh, ll;
                split4(v, hh, ll);
                *(uint2*)&img_h[row * IMG_PAD + kk0 + j * 4] = hh;
                *(uint2*)&img_l[row * IMG_PAD + kk0 + j * 4] = ll;
            }
            __syncthreads();
            // ldmatrix x4: rows (lane&15), k = kbase + ks*16 + (lane>>4)*8
            const uint32_t ao =
                (uint32_t)((lane & 15) * IMG_PAD + kbase + (lane >> 4) * 8) * 2u;
            #pragma unroll
            for (int ks = 0; ks < 4; ks++) {
                LDSM4(wh[mf][ks], uih + ao + (uint32_t)(ks * 16) * 2u);
                LDSM4(wl[mf][ks], uil + ao + (uint32_t)(ks * 16) * 2u);
            }
            __syncthreads();
        }
    }

    // steady-state smem: h rows (16 warps x 2304B = 36864B) + psm
    char* hwbase = smc;
    float* psm   = (float*)(smc + PSM_OFF);
    __nv_bfloat16* hw_h = (__nv_bfloat16*)(hwbase + warp * (2 * HW_WARP));
    __nv_bfloat16* hw_l = (__nv_bfloat16*)(hwbase + warp * (2 * HW_WARP) + HW_WARP);
    const uint32_t uhh = smem_to_u32(hw_h);
    const uint32_t uhl = smem_to_u32(hw_l);
    // B-frag address: batch row (lane&7), k-half ((lane>>3)&1)*8
    const uint32_t bo =
        (uint32_t)((lane & 7) * HW_PAD + ((lane >> 3) & 1) * 8) * 2u;

    const float* xp_ptr = g_xp + ((size_t)(b0 + warp) * LL) * HH + (c0 + lane);
    float*       r_ptr  = r    + ((size_t)(b0 + warp) * LL) * HH + (c0 + lane);

    for (int t = 0; t < LL; t++) {
        float xq = 0.0f;
        if (t > 0) {
            // wait for my TWO producer blocks (lanes 0-1 read the pair)
            unsigned f;
            do {
                unsigned v = (lane < 2) ? ld_acquire(poll_line + lane) : 0u;
                unsigned f0 = __shfl_sync(0xffffffffu, v, 0);
                unsigned f1 = __shfl_sync(0xffffffffu, v, 1);
                f = (f0 < f1) ? f0 : f1;
            } while (f < (unsigned)t);

            // warp-local h staging: 4 float4 per thread -> bf16 hi/lo smem
            const float* hsrc = r + (size_t)(t - 1) * HH + kbase;
            #pragma unroll
            for (int j = 0; j < 4; j++) {
                const int i  = j * 32 + lane;
                const int rr = i >> 4;            // 0..7 (batch row)
                const int qq = (i & 15) << 2;     // 0..60 (k)
                float4 v = *(const float4*)(hsrc + (size_t)(b0 + rr) * LL * HH + qq);
                uint2 hh, ll;
                split4(v, hh, ll);
                *(uint2*)&hw_h[rr * HW_PAD + qq] = hh;
                *(uint2*)&hw_l[rr * HW_PAD + qq] = ll;
            }
            __syncwarp();

            if (warp < 8) xq = __ldg(xp_ptr + (size_t)t * HH);

            float acc[2][4];
            #pragma unroll
            for (int mf = 0; mf < 2; mf++)
                #pragma unroll
                for (int i = 0; i < 4; i++) acc[mf][i] = 0.0f;

            #pragma unroll
            for (int ks = 0; ks < 4; ks++) {
                uint32_t bh[2], bl[2];
                const uint32_t ko = (uint32_t)(ks * 16) * 2u;
                LDSM2(bh, uhh + bo + ko);
                LDSM2(bl, uhl + bo + ko);
                #pragma unroll
                for (int mf = 0; mf < 2; mf++) {
                    MMA16816(acc[mf], wh[mf][ks], bh);
                    MMA16816(acc[mf], wh[mf][ks], bl);
                    MMA16816(acc[mf], wl[mf][ks], bh);
                }
            }

            // psm write: m = col-in-block, n = batch; stride 9 decorrelates banks
            #pragma unroll
            for (int mf = 0; mf < 2; mf++) {
                const int m = mf * 16 + (lane >> 2);
                const int n = (lane & 3) * 2;
                float* pw = psm + warp * PSM_STRIDE;
                pw[m * 9 + n]           = acc[mf][0];
                pw[m * 9 + n + 1]       = acc[mf][1];
                pw[(m + 8) * 9 + n]     = acc[mf][2];
                pw[(m + 8) * 9 + n + 1] = acc[mf][3];
            }
            __syncthreads();
        } else {
            if (warp < 8) xq = __ldg(xp_ptr);
        }

        // producers: reduce + activation + store + publish (warp = batch)
        if (warp < 8) {
            float dot = 0.0f;
            if (t > 0) {
                #pragma unroll
                for (int w = 0; w < 16; w++)
                    dot += psm[w * PSM_STRIDE + lane * 9 + warp];
            }
            r_ptr[(size_t)t * HH] = fast_tanh(xq + dot);

            if (t < LL - 1) {
                asm volatile("bar.sync 1, 256;" ::: "memory");
                if (tid == 0)
                    st_release(my_flag, (unsigned)(t + 1));
            }
        }
        // warps 8-15 fall through to the next iteration's flag poll
    }
}

__global__ void rnn_init_kernel()
{
    const int i = threadIdx.x;
    if (i < 128) g_done[(i >> 1) * 32 + (i & 1)] = 0u;
}

// ---------------------------------------------------------------------------
// Launch: 8 graph nodes
// ---------------------------------------------------------------------------
extern "C" void kernel_launch(void* const* d_in, const int* in_sizes, int n_in,
                              void* d_out, int out_size)
{
    const float* x     = (const float*)d_in[0];
    const float* W_ih1 = (const float*)d_in[1];
    const float* W_hh1 = (const float*)d_in[2];
    const float* b_ih1 = (const float*)d_in[3];
    const float* b_hh1 = (const float*)d_in[4];
    const float* W_ih2 = (const float*)d_in[5];
    const float* W_hh2 = (const float*)d_in[6];
    const float* b_ih2 = (const float*)d_in[7];
    const float* b_hh2 = (const float*)d_in[8];
    const float* W1    = (const float*)d_in[9];
    const float* b1    = (const float*)d_in[10];
    const float* W2    = (const float*)d_in[11];
    const float* b2    = (const float*)d_in[12];
    float* out = (float*)d_out;

    static int attr_set = 0;
    if (!attr_set) {
        cudaFuncSetAttribute(rnn_layer_kernel,
                             cudaFuncAttributeMaxDynamicSharedMemorySize,
                             RNN_SMEM_BYTES);
        attr_set = 1;
    }

    const dim3 gBig(HH / 128, BL / 128);   // (8, 128)
    const dim3 gOut(OO / 128, BL / 128);   // (1, 128)

    // xp = x @ W_ih1^T + b_ih1 + b_hh1
    mma_gemm<<<gBig, 256>>>(x, SEL_EXT, W_ih1,
                            nullptr, SEL_XP, b_ih1, b_hh1, HH, EE);
    // layer 1 recurrence
    rnn_init_kernel<<<1, 128>>>();
    rnn_layer_kernel<<<RNN_BLOCKS, 512, RNN_SMEM_BYTES>>>(SEL_R1, W_hh1);

    // xp = r1 @ W_ih2^T + b_ih2 + b_hh2
    mma_gemm<<<gBig, 256>>>(nullptr, SEL_R1, W_ih2,
                            nullptr, SEL_XP, b_ih2, b_hh2, HH, HH);
    // layer 2 recurrence
    rnn_init_kernel<<<1, 128>>>();
    rnn_layer_kernel<<<RNN_BLOCKS, 512, RNN_SMEM_BYTES>>>(SEL_R2, W_hh2);

    // y = r1 @ W1^T + b1 ; z = r2 @ W2^T + b2
    mma_gemm<<<gOut, 256>>>(nullptr, SEL_R1, W1,
                            out, SEL_EXT, b1, nullptr, OO, HH);
    mma_gemm<<<gOut, 256>>>(nullptr, SEL_R2, W2,
                            out + (size_t)BL * OO, SEL_EXT, b2, nullptr, OO, HH);
}